// round 11
// baseline (speedup 1.0000x reference)
#include <cuda_runtime.h>

// Problem constants (FullChain_58815282152074): N=4096 nodes, d=16, K=16, B=4
#define MB   1024          // nodes per batch (M)
#define NB   4             // num_batches
#define IG   4             // i's per block

// Scratch: effective bilinear weight WT[d][e][o] and effective bias
__device__ float g_WT[16 * 16 * 16];
__device__ float g_beff[16];

// ---- packed f32x2 helpers (Blackwell FFMA2) ----
__device__ __forceinline__ unsigned long long ffma2(unsigned long long a,
                                                    unsigned long long b,
                                                    unsigned long long c) {
    unsigned long long d;
    asm("fma.rn.f32x2 %0, %1, %2, %3;" : "=l"(d) : "l"(a), "l"(b), "l"(c));
    return d;
}
__device__ __forceinline__ unsigned long long pack2(float lo, float hi) {
    unsigned long long d;
    asm("mov.b64 %0, {%1, %2};"
        : "=l"(d) : "r"(__float_as_uint(lo)), "r"(__float_as_uint(hi)));
    return d;
}
__device__ __forceinline__ float2 unpack2(unsigned long long v) {
    unsigned int lo, hi;
    asm("mov.b64 {%0, %1}, %2;" : "=r"(lo), "=r"(hi) : "l"(v));
    return make_float2(__uint_as_float(lo), __uint_as_float(hi));
}

// ---------------------------------------------------------------------------
// Kernel A: fold W3@W2 into the bilinear form.
//   C[o,k]     = sum_t W3[o,t] * W2[t,k]
//   WT[d,e,o]  = sum_k C[o,k] * W_bil[k,d,e]     (stored [d][e][o])
//   beff[o]    = sum_k C[o,k]*b_bil[k] + sum_t W3[o,t]*b2[t] + b3[o]
// ---------------------------------------------------------------------------
__global__ void prep_kernel(const float* __restrict__ W_bil,
                            const float* __restrict__ b_bil,
                            const float* __restrict__ W2,
                            const float* __restrict__ b2,
                            const float* __restrict__ W3,
                            const float* __restrict__ b3) {
    __shared__ float Cs[256];
    int tid = threadIdx.x;
    {
        int o = tid >> 4, k = tid & 15;
        float s = 0.f;
#pragma unroll
        for (int t = 0; t < 16; ++t) s += W3[o * 16 + t] * W2[t * 16 + k];
        Cs[tid] = s;
    }
    __syncthreads();
    {
        int d = tid >> 4, e = tid & 15;
#pragma unroll
        for (int o = 0; o < 16; ++o) {
            float s = 0.f;
#pragma unroll
            for (int k = 0; k < 16; ++k)
                s += Cs[o * 16 + k] * W_bil[k * 256 + d * 16 + e];
            g_WT[(d * 16 + e) * 16 + o] = s;
        }
    }
    if (tid < 16) {
        int o = tid;
        float s = b3[o];
#pragma unroll
        for (int k = 0; k < 16; ++k) s += Cs[o * 16 + k] * b_bil[k];
#pragma unroll
        for (int t = 0; t < 16; ++t) s += W3[o * 16 + t] * b2[t];
        g_beff[o] = s;
    }
}

// ---------------------------------------------------------------------------
// Kernel B: one block per (b, group of IG=4 i's).  256 threads, 2 CTAs/SM.
//   Phase 0: stage batch X (1024x16 floats, stride 16, conflict-free).
//   Phase 1: T_i[e][o] for 4 i's, PAIR-INTERLEAVED over e:
//            T2sm[ii][e/2][o][2] = {T[e even], T[e odd]}   (256 floats/i).
//   Phase 2: lane = (j-slot = lane>>2, o-quad = lane&3); T2 for the o-quad
//            in 32 u64 regs.  jj loop is MODULO-2 SOFTWARE-PIPELINED with
//            two static x buffer sets (A/B): loads for the next j issue
//            before the current j's FFMA chain, with ZERO register copies
//            (the R6 rotation-MOV regression) — hides queued-LDS latency.
//            Tail overread lands in T2sm (in-bounds, unused).
// ---------------------------------------------------------------------------
__global__ __launch_bounds__(256, 2) void edge_kernel(const float* __restrict__ nodes,
                                                      float* __restrict__ out) {
    extern __shared__ float smem[];
    float* xs   = smem;                    // [MB][16]       64KB
    float* T2sm = smem + MB * 16;          // [IG][256]       4KB
    float* sbe  = T2sm + IG * 256;         // [16]

    const int tid = threadIdx.x;
    const int b   = blockIdx.x >> 8;       // 256 i-groups per batch
    const int ig  = blockIdx.x & 255;
    const int i0  = ig * IG;

    // ---- Phase 0: stage batch X into shared ----
    const float4* __restrict__ Xg = (const float4*)(nodes + (size_t)b * (MB * 16));
    float4* xs4 = (float4*)xs;
#pragma unroll
    for (int k = 0; k < 16; ++k) xs4[tid + k * 256] = Xg[tid + k * 256];
    if (tid < 16) sbe[tid] = g_beff[tid];
    __syncthreads();

    // ---- Phase 1: T for 4 i's, pair-interleaved over e ----
    {
        const int e = tid >> 4, o = tid & 15;
        float t0 = 0.f, t1 = 0.f, t2 = 0.f, t3 = 0.f;
#pragma unroll
        for (int d = 0; d < 16; ++d) {
            float w = g_WT[d * 256 + tid];
            t0 += xs[(i0 + 0) * 16 + d] * w;
            t1 += xs[(i0 + 1) * 16 + d] * w;
            t2 += xs[(i0 + 2) * 16 + d] * w;
            t3 += xs[(i0 + 3) * 16 + d] * w;
        }
        const int po = (e >> 1) * 32 + o * 2 + (e & 1);
        T2sm[0 * 256 + po] = t0;
        T2sm[1 * 256 + po] = t1;
        T2sm[2 * 256 + po] = t2;
        T2sm[3 * 256 + po] = t3;
    }
    __syncthreads();

    // ---- Phase 2: edges ----
    const int lane = tid & 31;
    const int warp = tid >> 5;
    const int q    = lane & 3;             // o-quad: outputs [4q, 4q+4)
    const int slot = lane >> 2;            // j-slot within warp (0..7)

    // bias in lo half, 0 in hi: final lo+hi fold includes bias exactly once
    const unsigned long long bias0 = pack2(sbe[4 * q + 0], 0.f);
    const unsigned long long bias1 = pack2(sbe[4 * q + 1], 0.f);
    const unsigned long long bias2v = pack2(sbe[4 * q + 2], 0.f);
    const unsigned long long bias3 = pack2(sbe[4 * q + 3], 0.f);

    const ulonglong2* __restrict__ X2 = (const ulonglong2*)xs;   // 16B units
    const int jb = warp * 128 + slot;
    const ulonglong2* __restrict__ xw = X2 + (size_t)jb * 4;

#pragma unroll 1
    for (int ii = 0; ii < IG; ++ii) {
        const int i = i0 + ii;

        // T2 for this lane's o-quad -> 32 u64 registers
        unsigned long long Ta[8], Tb[8], Tc[8], Td[8];
#pragma unroll
        for (int ep = 0; ep < 8; ++ep) {
            const float* base = T2sm + ii * 256 + ep * 32 + q * 8;
            ulonglong2 u = *(const ulonglong2*)(base);
            ulonglong2 v = *(const ulonglong2*)(base + 4);
            Ta[ep] = u.x; Tb[ep] = u.y; Tc[ep] = v.x; Td[ep] = v.y;
        }

        float* __restrict__ outBase =
            out + (size_t)(b * MB + i) * (MB - 1) * 16 + q * 4;

        // body: compute + store one edge from a loaded x set
        auto body = [&](ulonglong2 d0, ulonglong2 d1, ulonglong2 d2,
                        ulonglong2 d3, int jcur) {
            unsigned long long a0, a1, a2, a3;
            a0 = ffma2(Ta[0], d0.x, bias0);
            a1 = ffma2(Tb[0], d0.x, bias1);
            a2 = ffma2(Tc[0], d0.x, bias2v);
            a3 = ffma2(Td[0], d0.x, bias3);
            a0 = ffma2(Ta[1], d0.y, a0);  a1 = ffma2(Tb[1], d0.y, a1);
            a2 = ffma2(Tc[1], d0.y, a2);  a3 = ffma2(Td[1], d0.y, a3);
            a0 = ffma2(Ta[2], d1.x, a0);  a1 = ffma2(Tb[2], d1.x, a1);
            a2 = ffma2(Tc[2], d1.x, a2);  a3 = ffma2(Td[2], d1.x, a3);
            a0 = ffma2(Ta[3], d1.y, a0);  a1 = ffma2(Tb[3], d1.y, a1);
            a2 = ffma2(Tc[3], d1.y, a2);  a3 = ffma2(Td[3], d1.y, a3);
            a0 = ffma2(Ta[4], d2.x, a0);  a1 = ffma2(Tb[4], d2.x, a1);
            a2 = ffma2(Tc[4], d2.x, a2);  a3 = ffma2(Td[4], d2.x, a3);
            a0 = ffma2(Ta[5], d2.y, a0);  a1 = ffma2(Tb[5], d2.y, a1);
            a2 = ffma2(Tc[5], d2.y, a2);  a3 = ffma2(Td[5], d2.y, a3);
            a0 = ffma2(Ta[6], d3.x, a0);  a1 = ffma2(Tb[6], d3.x, a1);
            a2 = ffma2(Tc[6], d3.x, a2);  a3 = ffma2(Td[6], d3.x, a3);
            a0 = ffma2(Ta[7], d3.y, a0);  a1 = ffma2(Tb[7], d3.y, a1);
            a2 = ffma2(Tc[7], d3.y, a2);  a3 = ffma2(Td[7], d3.y, a3);

            if (jcur != i) {
                const int r = jcur - (jcur > i);
                float2 f0 = unpack2(a0), f1 = unpack2(a1);
                float2 f2 = unpack2(a2), f3 = unpack2(a3);
                *(float4*)(outBase + (size_t)r * 16) =
                    make_float4(f0.x + f0.y, f1.x + f1.y,
                                f2.x + f2.y, f3.x + f3.y);
            }
        };

        // modulo-2 software pipeline: load next set before computing current
        ulonglong2 A0 = xw[0], A1 = xw[1], A2 = xw[2], A3 = xw[3];
#pragma unroll 1
        for (int jj = 0; jj < 16; jj += 2) {
            const ulonglong2* xb = xw + (jj * 8 + 8) * 4;     // j+8
            ulonglong2 B0 = xb[0], B1 = xb[1], B2 = xb[2], B3 = xb[3];
            body(A0, A1, A2, A3, jb + jj * 8);

            const ulonglong2* xa = xw + (jj * 8 + 16) * 4;    // j+16
            // last step overreads into T2sm region: in-bounds, unused
            A0 = xa[0]; A1 = xa[1]; A2 = xa[2]; A3 = xa[3];
            body(B0, B1, B2, B3, jb + jj * 8 + 8);
        }
    }
}

extern "C" void kernel_launch(void* const* d_in, const int* in_sizes, int n_in,
                              void* d_out, int out_size) {
    const float* nodes = (const float*)d_in[0];
    const float* W_bil = (const float*)d_in[1];
    const float* b_bil = (const float*)d_in[2];
    const float* W2    = (const float*)d_in[3];
    const float* b2    = (const float*)d_in[4];
    const float* W3    = (const float*)d_in[5];
    const float* b3    = (const float*)d_in[6];
    float* out = (float*)d_out;

    const int smem_bytes = (MB * 16 + IG * 256 + 16) * (int)sizeof(float);
    static bool attr_set = false;
    if (!attr_set) {
        cudaFuncSetAttribute(edge_kernel,
                             cudaFuncAttributeMaxDynamicSharedMemorySize,
                             smem_bytes);
        attr_set = true;
    }

    prep_kernel<<<1, 256>>>(W_bil, b_bil, W2, b2, W3, b3);
    edge_kernel<<<NB * (MB / IG), 256, smem_bytes>>>(nodes, out);
}

// round 12
// speedup vs baseline: 1.0597x; 1.0597x over previous
#include <cuda_runtime.h>

// Problem constants (FullChain_58815282152074): N=4096 nodes, d=16, K=16, B=4
#define MB   1024          // nodes per batch (M)
#define NB   4             // num_batches
#define IG   4             // i's per block
#define XS_STRIDE 20       // padded floats per x-row (champion R6 layout)

// Scratch: effective bilinear weight WT[d][e][o] and effective bias
__device__ float g_WT[16 * 16 * 16];
__device__ float g_beff[16];

// ---- packed f32x2 helpers (Blackwell FFMA2) ----
__device__ __forceinline__ unsigned long long ffma2(unsigned long long a,
                                                    unsigned long long b,
                                                    unsigned long long c) {
    unsigned long long d;
    asm("fma.rn.f32x2 %0, %1, %2, %3;" : "=l"(d) : "l"(a), "l"(b), "l"(c));
    return d;
}
__device__ __forceinline__ unsigned long long pack2(float lo, float hi) {
    unsigned long long d;
    asm("mov.b64 %0, {%1, %2};"
        : "=l"(d) : "r"(__float_as_uint(lo)), "r"(__float_as_uint(hi)));
    return d;
}
__device__ __forceinline__ float2 unpack2(unsigned long long v) {
    unsigned int lo, hi;
    asm("mov.b64 {%0, %1}, %2;" : "=r"(lo), "=r"(hi) : "l"(v));
    return make_float2(__uint_as_float(lo), __uint_as_float(hi));
}

// ---------------------------------------------------------------------------
// Kernel A: fold W3@W2 into the bilinear form.
//   C[o,k]     = sum_t W3[o,t] * W2[t,k]
//   WT[d,e,o]  = sum_k C[o,k] * W_bil[k,d,e]     (stored [d][e][o])
//   beff[o]    = sum_k C[o,k]*b_bil[k] + sum_t W3[o,t]*b2[t] + b3[o]
// ---------------------------------------------------------------------------
__global__ void prep_kernel(const float* __restrict__ W_bil,
                            const float* __restrict__ b_bil,
                            const float* __restrict__ W2,
                            const float* __restrict__ b2,
                            const float* __restrict__ W3,
                            const float* __restrict__ b3) {
    __shared__ float Cs[256];
    int tid = threadIdx.x;
    {
        int o = tid >> 4, k = tid & 15;
        float s = 0.f;
#pragma unroll
        for (int t = 0; t < 16; ++t) s += W3[o * 16 + t] * W2[t * 16 + k];
        Cs[tid] = s;
    }
    __syncthreads();
    {
        int d = tid >> 4, e = tid & 15;
#pragma unroll
        for (int o = 0; o < 16; ++o) {
            float s = 0.f;
#pragma unroll
            for (int k = 0; k < 16; ++k)
                s += Cs[o * 16 + k] * W_bil[k * 256 + d * 16 + e];
            g_WT[(d * 16 + e) * 16 + o] = s;
        }
    }
    if (tid < 16) {
        int o = tid;
        float s = b3[o];
#pragma unroll
        for (int k = 0; k < 16; ++k) s += Cs[o * 16 + k] * b_bil[k];
#pragma unroll
        for (int t = 0; t < 16; ++t) s += W3[o * 16 + t] * b2[t];
        g_beff[o] = s;
    }
}

// ---------------------------------------------------------------------------
// Kernel B (champion R6 structure + jj unroll-4):
//   One block per (b, group of IG=4 i's).  256 threads, 2 CTAs/SM.
//   Phase 0: stage batch X (1024 x 16, padded stride 20) into shared.
//   Phase 1: T_i[e][o] for the 4 i's -> shared.
//   Phase 2: lane = (j-slot = lane>>2, o-quad = lane&3); T for the o-quad in
//            32 u64 registers; per warp-iter 8 edges:
//              4 broadcast LDS.128 (x) + 16 pack2 + 32 FFMA2 (2 chains)
//              + 1 warp-contiguous STG.128.
//   jj UNROLLED x4: LDS addresses become base+immediate and ptxas gets a
//   4-body window to hoist loads across FFMA chains (auto-pipelining with
//   zero register copies — the thing R8/R9's manual versions got wrong).
// ---------------------------------------------------------------------------
__global__ __launch_bounds__(256, 2) void edge_kernel(const float* __restrict__ nodes,
                                                      float* __restrict__ out) {
    extern __shared__ float smem[];
    float* xs  = smem;                       // [MB][XS_STRIDE]  80KB
    float* Tsm = smem + MB * XS_STRIDE;      // [IG][256]        4KB
    float* sbe = Tsm + IG * 256;             // [16]

    const int tid = threadIdx.x;
    const int b   = blockIdx.x >> 8;         // 256 i-groups per batch
    const int ig  = blockIdx.x & 255;
    const int i0  = ig * IG;

    // ---- Phase 0: stage batch X into padded shared ----
    const float4* __restrict__ Xg = (const float4*)(nodes + (size_t)b * (MB * 16));
#pragma unroll
    for (int k = 0; k < 16; ++k) {
        int idx = tid + k * 256;             // float4 index, coalesced
        float4 v = Xg[idx];
        int row = idx >> 2, c = idx & 3;
        *(float4*)(xs + row * XS_STRIDE + c * 4) = v;
    }
    if (tid < 16) sbe[tid] = g_beff[tid];
    __syncthreads();

    // ---- Phase 1: T for the 4 i's (tid = e*16+o) ----
    {
        float t0 = 0.f, t1 = 0.f, t2 = 0.f, t3 = 0.f;
#pragma unroll
        for (int d = 0; d < 16; ++d) {
            float w = g_WT[d * 256 + tid];
            t0 += xs[(i0 + 0) * XS_STRIDE + d] * w;
            t1 += xs[(i0 + 1) * XS_STRIDE + d] * w;
            t2 += xs[(i0 + 2) * XS_STRIDE + d] * w;
            t3 += xs[(i0 + 3) * XS_STRIDE + d] * w;
        }
        Tsm[0 * 256 + tid] = t0;
        Tsm[1 * 256 + tid] = t1;
        Tsm[2 * 256 + tid] = t2;
        Tsm[3 * 256 + tid] = t3;
    }
    __syncthreads();

    // ---- Phase 2: edges ----
    const int lane = tid & 31;
    const int warp = tid >> 5;
    const int q    = lane & 3;               // o-quad: outputs [4q, 4q+4)
    const int slot = lane >> 2;              // j-slot within warp (0..7)

    const unsigned long long bias0 = pack2(sbe[4 * q],     sbe[4 * q + 1]);
    const unsigned long long bias1 = pack2(sbe[4 * q + 2], sbe[4 * q + 3]);

    const int jb = warp * 128 + slot;
    const float* __restrict__ xbase = xs + jb * XS_STRIDE;

#pragma unroll 1
    for (int ii = 0; ii < IG; ++ii) {
        const int i = i0 + ii;

        // T[:, 4q..4q+4) into registers (broadcast LDS.128, conflict-free)
        unsigned long long T0[16], T1[16];
#pragma unroll
        for (int e = 0; e < 16; ++e) {
            ulonglong2 tt = *(const ulonglong2*)(Tsm + ii * 256 + e * 16 + q * 4);
            T0[e] = tt.x;
            T1[e] = tt.y;
        }

        float* __restrict__ outBase =
            out + (size_t)(b * MB + i) * (MB - 1) * 16 + q * 4;

#pragma unroll 4
        for (int jj = 0; jj < 16; ++jj) {
            const int j = jb + jj * 8;

            // x_j: 4 LDS.128 at base+immediate (after unroll), conflict-free
            const float* xr = xbase + jj * (8 * XS_STRIDE);
            float4 v0 = *(const float4*)(xr);
            float4 v1 = *(const float4*)(xr + 4);
            float4 v2 = *(const float4*)(xr + 8);
            float4 v3 = *(const float4*)(xr + 12);
            float x[16] = {v0.x, v0.y, v0.z, v0.w, v1.x, v1.y, v1.z, v1.w,
                           v2.x, v2.y, v2.z, v2.w, v3.x, v3.y, v3.z, v3.w};

            unsigned long long acc0 = bias0;
            unsigned long long acc1 = bias1;
#pragma unroll
            for (int e = 0; e < 16; ++e) {
                unsigned long long xx = pack2(x[e], x[e]);
                acc0 = ffma2(T0[e], xx, acc0);
                acc1 = ffma2(T1[e], xx, acc1);
            }

            if (j != i) {
                const int r = j - (j > i);
                float2 lo = unpack2(acc0);
                float2 hi = unpack2(acc1);
                *(float4*)(outBase + (size_t)r * 16) =
                    make_float4(lo.x, lo.y, hi.x, hi.y);
            }
        }
    }
}

extern "C" void kernel_launch(void* const* d_in, const int* in_sizes, int n_in,
                              void* d_out, int out_size) {
    const float* nodes = (const float*)d_in[0];
    const float* W_bil = (const float*)d_in[1];
    const float* b_bil = (const float*)d_in[2];
    const float* W2    = (const float*)d_in[3];
    const float* b2    = (const float*)d_in[4];
    const float* W3    = (const float*)d_in[5];
    const float* b3    = (const float*)d_in[6];
    float* out = (float*)d_out;

    const int smem_bytes = (MB * XS_STRIDE + IG * 256 + 16) * (int)sizeof(float);
    static bool attr_set = false;
    if (!attr_set) {
        cudaFuncSetAttribute(edge_kernel,
                             cudaFuncAttributeMaxDynamicSharedMemorySize,
                             smem_bytes);
        attr_set = true;
    }

    prep_kernel<<<1, 256>>>(W_bil, b_bil, W2, b2, W3, b3);
    edge_kernel<<<NB * (MB / IG), 256, smem_bytes>>>(nodes, out);
}